// round 14
// baseline (speedup 1.0000x reference)
#include <cuda_runtime.h>
#include <cuda_fp16.h>

// SparseAttention (entmax-1.5), GB300 sm_103a. Round 13: INT8 IMMA mainloop
// (R12 fixed: cvt_kernel grid was 2x oversized -> OOB writes -> illegal access).
//  - Q,K quantized to int8 (scale 23); quant error ~0.2 score units rms, inside
//    the 3.5 collect window -> candidate superset preserved; exact fp32 rescore
//    tail keeps the final output bit-identical.
//  - mma.sync.m16n8k32.s8.s32: half the ldsm/mma instructions of the f16 path.
//  - integer-domain running row max + threshold, collect stores indices only.
//  - group-private K staging with named barriers (R11), 4 stages.

#define BATCH 8
#define SEQ   2048
#define DIM   128
#define BM    128
#define BN    128
#define NT    (SEQ / BN)       // 16
#define PAIRS (NT / 2)         // 8
#define QT    (SEQ / BM)       // 16
#define CAP   48
#define CSTR  49
#define RB    144              // int8 row bytes (128 data + 16 pad): ldsm conflict-free
#define NITER 100
#define NTHREADS 1024
#define ZREG  12
#define QSCALE 23.0f
#define THR_I  1852            // ceil(3.5 * 23 * 23)

#define TILE_B  (BM * RB)                             // 18432
#define OFF_QHI  0
#define OFF_KHI  (OFF_QHI + TILE_B)                   // 18432
#define OFF_CS   (OFF_KHI + 4 * TILE_B)               // 92160
#define OFF_CC   (OFF_CS + BM * CSTR * 4)             // 117248
#define OFF_RM   (OFF_CC + BM * CSTR * 4)             // 142336
#define OFF_CNT  (OFF_RM + BM * 4)                    // 142848
#define OFF_TAU  (OFF_CNT + BM * 4)                   // 143360
#define OFF_Z    (OFF_TAU + BM * 4)                   // 143872
#define SMEM_BYTES (OFF_Z + BM * 4)                   // 144384

__device__ signed char g_Qi[BATCH * SEQ * DIM];
__device__ signed char g_Ki[BATCH * SEQ * DIM];

__global__ void cvt_kernel(const float* __restrict__ Q, const float* __restrict__ K) {
    size_t i = ((size_t)blockIdx.x * blockDim.x + threadIdx.x) * 4;
    float4 q = *(const float4*)(Q + i);
    float4 k = *(const float4*)(K + i);
    char4 qc, kc;
    qc.x = (signed char)max(-127, min(127, __float2int_rn(q.x * QSCALE)));
    qc.y = (signed char)max(-127, min(127, __float2int_rn(q.y * QSCALE)));
    qc.z = (signed char)max(-127, min(127, __float2int_rn(q.z * QSCALE)));
    qc.w = (signed char)max(-127, min(127, __float2int_rn(q.w * QSCALE)));
    kc.x = (signed char)max(-127, min(127, __float2int_rn(k.x * QSCALE)));
    kc.y = (signed char)max(-127, min(127, __float2int_rn(k.y * QSCALE)));
    kc.z = (signed char)max(-127, min(127, __float2int_rn(k.z * QSCALE)));
    kc.w = (signed char)max(-127, min(127, __float2int_rn(k.w * QSCALE)));
    *(char4*)(g_Qi + i) = qc;
    *(char4*)(g_Ki + i) = kc;
}

static __device__ __forceinline__ void cpasync16(unsigned dst, const void* src) {
    asm volatile("cp.async.cg.shared.global [%0], [%1], 16;\n" :: "r"(dst), "l"(src));
}
static __device__ __forceinline__ void cp_commit() {
    asm volatile("cp.async.commit_group;\n");
}
template <int N>
static __device__ __forceinline__ void cp_wait() {
    asm volatile("cp.async.wait_group %0;\n" :: "n"(N));
}
static __device__ __forceinline__ void nbar(int id) {
    asm volatile("bar.sync %0, %1;" :: "r"(id), "r"(128) : "memory");
}
static __device__ __forceinline__ void ldsm4(unsigned* r, unsigned addr) {
    asm volatile("ldmatrix.sync.aligned.m8n8.x4.shared.b16 {%0,%1,%2,%3}, [%4];\n"
                 : "=r"(r[0]), "=r"(r[1]), "=r"(r[2]), "=r"(r[3])
                 : "r"(addr) : "memory");
}
// s8 x s8 -> s32, m16n8k32
static __device__ __forceinline__ void mma16832i(int* c, const unsigned* a, const unsigned* b) {
    asm volatile("mma.sync.aligned.m16n8k32.row.col.s32.s8.s8.s32 "
                 "{%0,%1,%2,%3}, {%4,%5,%6,%7}, {%8,%9}, {%0,%1,%2,%3};\n"
                 : "+r"(c[0]), "+r"(c[1]), "+r"(c[2]), "+r"(c[3])
                 : "r"(a[0]), "r"(a[1]), "r"(a[2]), "r"(a[3]),
                   "r"(b[0]), "r"(b[1]));
}

__global__ __launch_bounds__(NTHREADS, 1)
void entmax_attn_kernel(const float* __restrict__ Q, const float* __restrict__ K,
                        const float* __restrict__ V, float* __restrict__ O)
{
    extern __shared__ unsigned char smem[];
    float* candS = (float*)(smem + OFF_CS);
    int*   candC = (int*)(smem + OFF_CC);
    int*   rowM  = (int*)(smem + OFF_RM);
    int*   cnt   = (int*)(smem + OFF_CNT);
    float* tauA  = (float*)(smem + OFF_TAU);
    float* zA    = (float*)(smem + OFF_Z);

    const int tid  = threadIdx.x;
    const int lane = tid & 31;
    const int wid  = tid >> 5;
    const int b    = blockIdx.y;
    const int q0   = blockIdx.x * BM;

    const float* Qb = Q + ((size_t)b * SEQ + q0) * DIM;
    const float* Kb = K + (size_t)b * SEQ * DIM;
    const float* Vb = V + (size_t)b * SEQ * DIM;
    const signed char* Qib = g_Qi + ((size_t)b * SEQ + q0) * DIM;
    const signed char* Kib = g_Ki + (size_t)b * SEQ * DIM;

    const unsigned smemB = (unsigned)__cvta_generic_to_shared(smem);
    const unsigned qS = smemB + OFF_QHI;

    // 4x8 warp grid: warp tile 32(M) x 16(N); group = wn (4 warps, contiguous tids)
    const int wm = wid & 3;
    const int wn = wid >> 2;
    const int g  = lane >> 2;
    const int t  = lane & 3;

    const int aRow = (lane & 7) + ((lane >> 3) & 1) * 8;  // ldsm x4 (A)
    const int aKb  = ((lane >> 4) & 1) * 16;              // byte offset within 32B k-chunk
    const int bGrp  = lane >> 3;                          // ldsm x4 (B)
    const int bRow4 = ((bGrp >> 1) & 1) * 8 + (lane & 7);
    const int bKb4  = (bGrp & 1) * 16;

    if (tid < BM) { rowM[tid] = (int)0x80000000; cnt[tid] = 0; }

    // ---- Q fill: 128 rows x 8 chunks(16B) = 1024 -> 1 per thread ----
    {
        const int fr = tid >> 3;
        const int fc = tid & 7;
        cpasync16(qS + fr * RB + fc * 16, Qib + fr * DIM + fc * 16);
    }

    // ---- group-private slice fill: 16 rows x 8 chunks / 128 threads = 1 each ----
    const int slr = (tid & 127) >> 3;        // 0..15
    const int sc  = (tid & 127) & 7;         // 0..7
    const int srow = wn * 16 + slr;
    auto fill_slice = [&](int nt) {
        cpasync16(smemB + OFF_KHI + (nt & 3) * TILE_B + srow * RB + sc * 16,
                  Kib + (size_t)nt * BN * DIM + srow * DIM + sc * 16);
    };

    fill_slice(0);
    cp_commit();                 // G0 = Q + tile0
    fill_slice(1);
    cp_commit();                 // G1 = tile1
    fill_slice(2);
    fill_slice(3);
    cp_commit();                 // G2 = pair1
    cp_wait<2>();                // G0 done
    __syncthreads();             // Q visible to all warps

    const unsigned aAddr0 = qS + (unsigned)((wm * 32 + aRow) * RB + aKb);
    const unsigned aAddr1 = qS + (unsigned)((wm * 32 + 16 + aRow) * RB + aKb);
    const unsigned bOff   = (unsigned)((wn * 16 + bRow4) * RB + bKb4);
    const int barid = wn + 1;

    auto process_tile = [&](unsigned kS, int nt) {
        int acc[2][2][4];
        #pragma unroll
        for (int m = 0; m < 2; m++)
            #pragma unroll
            for (int n = 0; n < 2; n++)
                #pragma unroll
                for (int e = 0; e < 4; e++) acc[m][n][e] = 0;

        #pragma unroll
        for (int ks = 0; ks < 4; ks++) {
            unsigned a[2][4], bb[4];
            ldsm4(a[0], aAddr0 + ks * 32);
            ldsm4(a[1], aAddr1 + ks * 32);
            ldsm4(bb, kS + ks * 32);
            #pragma unroll
            for (int m = 0; m < 2; m++) {
                mma16832i(acc[m][0], a[m], &bb[0]);
                mma16832i(acc[m][1], a[m], &bb[2]);
            }
        }

        // integer running row max + collect
        int qm[2][2];
        #pragma unroll
        for (int m = 0; m < 2; m++) {
            #pragma unroll
            for (int h = 0; h < 2; h++) {
                int lm = max(max(acc[m][0][h * 2], acc[m][0][h * 2 + 1]),
                             max(acc[m][1][h * 2], acc[m][1][h * 2 + 1]));
                lm = max(lm, __shfl_xor_sync(0xffffffffu, lm, 1));
                lm = max(lm, __shfl_xor_sync(0xffffffffu, lm, 2));
                qm[m][h] = lm;
                if ((lane & 3) == 0) {
                    const int r = wm * 32 + m * 16 + h * 8 + g;
                    if (lm > rowM[r]) atomicMax(&rowM[r], lm);
                }
            }
        }
        __syncwarp();
        #pragma unroll
        for (int m = 0; m < 2; m++) {
            #pragma unroll
            for (int h = 0; h < 2; h++) {
                const int r = wm * 32 + m * 16 + h * 8 + g;
                const int thr = rowM[r] - THR_I;
                if (qm[m][h] > thr) {
                    #pragma unroll
                    for (int n = 0; n < 2; n++) {
                        #pragma unroll
                        for (int e = 0; e < 2; e++) {
                            int s = acc[m][n][h * 2 + e];
                            if (s > thr) {
                                int p = atomicAdd(&cnt[r], 1);
                                if (p < CAP)
                                    candC[r * CSTR + p] = nt * BN + wn * 16 + n * 8 + t * 2 + e;
                            }
                        }
                    }
                }
            }
        }
    };

    for (int pp = 0; pp < PAIRS; pp++) {
        {   // pair pp ready when groups 0..pp+1 done; commits = 3 + min(pp, PAIRS-2)
            const int commits = 3 + (pp < PAIRS - 2 ? pp : PAIRS - 2);
            const int out     = commits - (pp + 2);
            if (out <= 0)      cp_wait<0>();
            else if (out == 1) cp_wait<1>();
            else               cp_wait<2>();
        }
        nbar(barid);

        const int t0 = 2 * pp, t1 = 2 * pp + 1;
        process_tile(smemB + OFF_KHI + (t0 & 3) * TILE_B + bOff, t0);
        process_tile(smemB + OFF_KHI + (t1 & 3) * TILE_B + bOff, t1);

        nbar(barid);             // group done reading pair pp's slices
        if (pp + 2 < PAIRS) {
            fill_slice(2 * pp + 4);
            fill_slice(2 * pp + 5);
            cp_commit();
        }
    }
    __syncthreads();

    // ---- deterministic order: per-row insertion sort by column (indices) ----
    if (tid < BM) {
        const int r = tid;
        int c_ = cnt[r]; if (c_ > CAP) { c_ = CAP; cnt[r] = CAP; }
        int* cc = candC + r * CSTR;
        for (int i = 1; i < c_; i++) {
            int kv = cc[i]; int j = i - 1;
            while (j >= 0 && cc[j] > kv) { cc[j + 1] = cc[j]; j--; }
            cc[j + 1] = kv;
        }
    }
    __syncthreads();

    // ---- exact fp32 rescore: warp-per-row (4 rows/warp), 4-way batched LDG ----
    for (int r = wid; r < BM; r += 32) {
        const int c_ = cnt[r];
        float* cs = candS + r * CSTR;
        int*   cc = candC + r * CSTR;
        const float4 qv = *(const float4*)(Qb + (size_t)r * DIM + lane * 4);
        for (int j0 = 0; j0 < c_; j0 += 4) {
            float4 kv[4];
            #pragma unroll
            for (int u = 0; u < 4; u++) {
                int j = j0 + u; if (j >= c_) j = c_ - 1;
                kv[u] = *(const float4*)(Kb + (size_t)cc[j] * DIM + lane * 4);
            }
            float d[4];
            #pragma unroll
            for (int u = 0; u < 4; u++) {
                float s = fmaf(qv.x, kv[u].x, 0.f);
                s = fmaf(qv.y, kv[u].y, s);
                s = fmaf(qv.z, kv[u].z, s);
                d[u] = fmaf(qv.w, kv[u].w, s);
            }
            #pragma unroll
            for (int s = 16; s > 0; s >>= 1) {
                d[0] += __shfl_xor_sync(0xffffffffu, d[0], s);
                d[1] += __shfl_xor_sync(0xffffffffu, d[1], s);
                d[2] += __shfl_xor_sync(0xffffffffu, d[2], s);
                d[3] += __shfl_xor_sync(0xffffffffu, d[3], s);
            }
            if (lane == 0) {
                #pragma unroll
                for (int u = 0; u < 4; u++)
                    if (j0 + u < c_) cs[j0 + u] = d[u];
            }
        }
    }
    __syncthreads();

    // ---- bisection: thread-per-row, register-resident z for c_<=ZREG ----
    if (tid < BM) {
        const int r = tid;
        const int c_ = cnt[r];
        float* cs = candS + r * CSTR;
        float tau, Zv;

        if (c_ <= ZREG) {
            float z[ZREG];
            float zmax = -3.0e38f;
            #pragma unroll
            for (int j = 0; j < ZREG; j++) {
                z[j] = (j < c_) ? 0.5f * cs[j] : -3.0e38f;
                zmax = fmaxf(zmax, z[j]);
            }
            float tmin = zmax - 1.0f;
            float tmax = zmax - 0.022097086912079608f;   // float32(2048^-0.5)
            tau = 0.5f * (tmin + tmax); Zv = 0.f;
            for (int it = 0; it < NITER; it++) {
                tau = 0.5f * (tmin + tmax);
                Zv = 0.f;
                #pragma unroll
                for (int j = 0; j < ZREG; j++) {
                    float dz = fmaxf(z[j] - tau, 0.f);
                    Zv = fmaf(dz, dz, Zv);
                }
                if (Zv >= 1.0f) tmin = tau; else tmax = tau;
            }
        } else {
            float smax = -3.0e38f;
            for (int j = 0; j < c_; j++) smax = fmaxf(smax, cs[j]);
            const float zmax = 0.5f * smax;
            float tmin = zmax - 1.0f;
            float tmax = zmax - 0.022097086912079608f;
            tau = 0.5f * (tmin + tmax); Zv = 0.f;
            for (int it = 0; it < NITER; it++) {
                tau = 0.5f * (tmin + tmax);
                Zv = 0.f;
                for (int j = 0; j < c_; j++) {
                    float dz = fmaxf(0.5f * cs[j] - tau, 0.f);
                    Zv = fmaf(dz, dz, Zv);
                }
                if (Zv >= 1.0f) tmin = tau; else tmax = tau;
            }
        }
        tauA[r] = tau;
        zA[r]   = Zv;
    }
    __syncthreads();

    // ---- sparse P@V: 32 warps x 4 rows, 4-way batched V gather ----
    for (int rr = 0; rr < 4; rr++) {
        const int r = wid * 4 + rr;
        const int c_ = cnt[r];
        const float tau = tauA[r];
        const float Zv  = zA[r];
        float ax = 0.f, ay = 0.f, az = 0.f, aw = 0.f;
        for (int j0 = 0; j0 < c_; j0 += 4) {
            float4 v[4]; float w[4];
            #pragma unroll
            for (int u = 0; u < 4; u++) {
                int j = j0 + u;
                bool ok = (j < c_);
                int jc = ok ? j : (c_ - 1);
                float dz = fmaxf(0.5f * candS[r * CSTR + jc] - tau, 0.f);
                w[u] = ok ? (dz * dz) / Zv : 0.f;
                v[u] = *(const float4*)(Vb + (size_t)candC[r * CSTR + jc] * DIM + lane * 4);
            }
            #pragma unroll
            for (int u = 0; u < 4; u++) {
                ax = fmaf(w[u], v[u].x, ax);
                ay = fmaf(w[u], v[u].y, ay);
                az = fmaf(w[u], v[u].z, az);
                aw = fmaf(w[u], v[u].w, aw);
            }
        }
        *(float4*)(O + ((size_t)b * SEQ + q0 + r) * DIM + lane * 4) = make_float4(ax, ay, az, aw);
    }
}

extern "C" void kernel_launch(void* const* d_in, const int* in_sizes, int n_in,
                              void* d_out, int out_size) {
    const float* Q = (const float*)d_in[0];
    const float* K = (const float*)d_in[1];
    const float* V = (const float*)d_in[2];
    float* O = (float*)d_out;

    cvt_kernel<<<2048, 256>>>(Q, K);   // 2048*256*4 = BATCH*SEQ*DIM exactly

    cudaFuncSetAttribute(entmax_attn_kernel,
                         cudaFuncAttributeMaxDynamicSharedMemorySize, SMEM_BYTES);
    dim3 grid(QT, BATCH);
    entmax_attn_kernel<<<grid, NTHREADS, SMEM_BYTES>>>(Q, K, V, O);
}

// round 15
// speedup vs baseline: 1.2687x; 1.2687x over previous
#include <cuda_runtime.h>
#include <cuda_fp16.h>

// SparseAttention (entmax-1.5), GB300 sm_103a. Round 14: SPLIT kernels.
//  - Kernel A (mainloop): R11 f16 IMMA structure (group-private K staging,
//    named barriers, pair A-reuse); dumps per-row candidate indices to global.
//  - Kernel B (tail): 512 blocks x 256 thr, 32 rows/block: sort + exact fp32
//    rescore + reg-resident bisection + sparse P@V. 4x tail parallelism.
//  - Split also gives per-kernel ncu timing (diagnostic for the stall budget).

#define BATCH 8
#define SEQ   2048
#define DIM   128
#define BM    128
#define BN    128
#define NT    (SEQ / BN)       // 16
#define PAIRS (NT / 2)         // 8
#define QT    (SEQ / BM)       // 16
#define CAP   48
#define CSTR  49
#define QSTR  136              // f16 row stride (128+8 pad): 16B aligned, ldsm conflict-free
#define NITER 100
#define NTHREADS 1024
#define ZREG  12
#define TROWS 32               // rows per tail block

#define TILE_B  (BM * QSTR * 2)                       // 34816
#define OFF_QHI  0
#define OFF_KHI  (OFF_QHI + TILE_B)                   // 34816
#define OFF_CC   (OFF_KHI + 4 * TILE_B)               // 174080
#define OFF_RM   (OFF_CC + BM * CSTR * 4)             // 199168
#define OFF_CNT  (OFF_RM + BM * 4)                    // 199680
#define SMEM_BYTES (OFF_CNT + BM * 4)                 // 200192

__device__ __half g_Qh[BATCH * SEQ * DIM];
__device__ __half g_Kh[BATCH * SEQ * DIM];
__device__ int    g_candC[BATCH * SEQ * CAP];
__device__ int    g_cnt[BATCH * SEQ];

__global__ void cvt_kernel(const float* __restrict__ Q, const float* __restrict__ K) {
    size_t i = ((size_t)blockIdx.x * blockDim.x + threadIdx.x) * 4;
    float4 q = *(const float4*)(Q + i);
    float4 k = *(const float4*)(K + i);
    *(__half2*)(g_Qh + i)     = __floats2half2_rn(q.x, q.y);
    *(__half2*)(g_Qh + i + 2) = __floats2half2_rn(q.z, q.w);
    *(__half2*)(g_Kh + i)     = __floats2half2_rn(k.x, k.y);
    *(__half2*)(g_Kh + i + 2) = __floats2half2_rn(k.z, k.w);
}

static __device__ __forceinline__ unsigned fenc(float f) {
    unsigned u = __float_as_uint(f);
    return (u & 0x80000000u) ? ~u : (u | 0x80000000u);
}
static __device__ __forceinline__ float fdec(unsigned e) {
    return (e & 0x80000000u) ? __uint_as_float(e & 0x7fffffffu)
                             : __uint_as_float(~e);
}
static __device__ __forceinline__ void cpasync16(unsigned dst, const void* src) {
    asm volatile("cp.async.cg.shared.global [%0], [%1], 16;\n" :: "r"(dst), "l"(src));
}
static __device__ __forceinline__ void cp_commit() {
    asm volatile("cp.async.commit_group;\n");
}
template <int N>
static __device__ __forceinline__ void cp_wait() {
    asm volatile("cp.async.wait_group %0;\n" :: "n"(N));
}
static __device__ __forceinline__ void nbar(int id) {
    asm volatile("bar.sync %0, %1;" :: "r"(id), "r"(128) : "memory");
}
static __device__ __forceinline__ void ldsm4(unsigned* r, unsigned addr) {
    asm volatile("ldmatrix.sync.aligned.m8n8.x4.shared.b16 {%0,%1,%2,%3}, [%4];\n"
                 : "=r"(r[0]), "=r"(r[1]), "=r"(r[2]), "=r"(r[3])
                 : "r"(addr) : "memory");
}
static __device__ __forceinline__ void mma16816h(unsigned* c, const unsigned* a, const unsigned* b) {
    asm volatile("mma.sync.aligned.m16n8k16.row.col.f16.f16.f16.f16 "
                 "{%0,%1}, {%2,%3,%4,%5}, {%6,%7}, {%0,%1};\n"
                 : "+r"(c[0]), "+r"(c[1])
                 : "r"(a[0]), "r"(a[1]), "r"(a[2]), "r"(a[3]),
                   "r"(b[0]), "r"(b[1]));
}

// ======================= Kernel A: mainloop =======================
__global__ __launch_bounds__(NTHREADS, 1)
void mainloop_kernel(const float* __restrict__ Q, const float* __restrict__ K)
{
    extern __shared__ unsigned char smem[];
    int*      candC = (int*)(smem + OFF_CC);
    unsigned* rowM  = (unsigned*)(smem + OFF_RM);
    int*      cnt   = (int*)(smem + OFF_CNT);

    const int tid  = threadIdx.x;
    const int lane = tid & 31;
    const int wid  = tid >> 5;
    const int b    = blockIdx.y;
    const int q0   = blockIdx.x * BM;

    const __half* Qhb = g_Qh + ((size_t)b * SEQ + q0) * DIM;
    const __half* Khb = g_Kh + (size_t)b * SEQ * DIM;

    const unsigned smemB = (unsigned)__cvta_generic_to_shared(smem);
    const unsigned qS = smemB + OFF_QHI;

    const int wm = wid & 3;
    const int wn = wid >> 2;
    const int g  = lane >> 2;
    const int t  = lane & 3;

    const int aRow = (lane & 7) + ((lane >> 3) & 1) * 8;
    const int aK   = ((lane >> 4) & 1) * 8;
    const int bGrp  = lane >> 3;
    const int bRow4 = ((bGrp >> 1) & 1) * 8 + (lane & 7);
    const int bK4   = (bGrp & 1) * 8;

    if (tid < BM) { rowM[tid] = 0u; cnt[tid] = 0; }

    // Q fill: all threads, 2 chunks each
    {
        const int fr0 = tid >> 4;
        const int fc  = tid & 15;
        #pragma unroll
        for (int k = 0; k < 2; k++) {
            int r = fr0 + k * 64;
            cpasync16(qS + r * (QSTR * 2) + fc * 16, Qhb + r * DIM + fc * 8);
        }
    }

    // group-private slice fill: 16 rows x 16 chunks / 128 threads = 2 each
    const int slr = (tid & 127) >> 3;
    const int sc0 = ((tid & 127) & 7) * 2;
    const int srow = wn * 16 + slr;
    auto fill_slice = [&](int nt) {
        unsigned dst = smemB + OFF_KHI + (nt & 3) * TILE_B + srow * (QSTR * 2);
        const __half* src = Khb + (size_t)nt * BN * DIM + srow * DIM;
        cpasync16(dst + sc0 * 16,       src + sc0 * 8);
        cpasync16(dst + (sc0 + 1) * 16, src + (sc0 + 1) * 8);
    };

    fill_slice(0);
    cp_commit();                 // G0 = Q + tile0
    fill_slice(1);
    cp_commit();                 // G1
    fill_slice(2);
    fill_slice(3);
    cp_commit();                 // G2 (pair1)
    cp_wait<2>();
    __syncthreads();             // Q visible

    const unsigned aAddr0 = qS + (unsigned)(((wm * 32 + aRow) * QSTR + aK) * 2);
    const unsigned aAddr1 = qS + (unsigned)(((wm * 32 + 16 + aRow) * QSTR + aK) * 2);
    const unsigned bOff   = (unsigned)(((wn * 16 + bRow4) * QSTR + bK4) * 2);
    const int barid = wn + 1;

    auto maxcollect = [&](unsigned (&acc)[2][2][2], int nt) {
        float qm[2][2];
        #pragma unroll
        for (int m = 0; m < 2; m++) {
            #pragma unroll
            for (int h = 0; h < 2; h++) {
                __half2 x = __hmax2(*(__half2*)&acc[m][0][h], *(__half2*)&acc[m][1][h]);
                float2 f = __half22float2(x);
                float lm = fmaxf(f.x, f.y);
                lm = fmaxf(lm, __shfl_xor_sync(0xffffffffu, lm, 1));
                lm = fmaxf(lm, __shfl_xor_sync(0xffffffffu, lm, 2));
                qm[m][h] = lm;
                if ((lane & 3) == 0) {
                    const int r = wm * 32 + m * 16 + h * 8 + g;
                    if (fenc(lm) > rowM[r]) atomicMax(&rowM[r], fenc(lm));
                }
            }
        }
        __syncwarp();
        #pragma unroll
        for (int m = 0; m < 2; m++) {
            #pragma unroll
            for (int h = 0; h < 2; h++) {
                const int r = wm * 32 + m * 16 + h * 8 + g;
                const float thr = fdec(rowM[r]) - 3.5f;
                if (qm[m][h] > thr) {
                    #pragma unroll
                    for (int n = 0; n < 2; n++) {
                        float2 f = __half22float2(*(__half2*)&acc[m][n][h]);
                        #pragma unroll
                        for (int e = 0; e < 2; e++) {
                            float s = (e == 0) ? f.x : f.y;
                            if (s > thr) {
                                int p = atomicAdd(&cnt[r], 1);
                                if (p < CAP)
                                    candC[r * CSTR + p] = nt * BN + wn * 16 + n * 8 + t * 2 + e;
                            }
                        }
                    }
                }
            }
        }
    };

    for (int pp = 0; pp < PAIRS; pp++) {
        {
            const int commits = 3 + (pp < PAIRS - 2 ? pp : PAIRS - 2);
            const int out     = commits - (pp + 2);
            if (out <= 0)      cp_wait<0>();
            else if (out == 1) cp_wait<1>();
            else               cp_wait<2>();
        }
        nbar(barid);

        const int t0 = 2 * pp, t1 = 2 * pp + 1;
        const unsigned kS0 = smemB + OFF_KHI + (t0 & 3) * TILE_B + bOff;
        const unsigned kS1 = smemB + OFF_KHI + (t1 & 3) * TILE_B + bOff;

        unsigned acc0[2][2][2], acc1[2][2][2];
        #pragma unroll
        for (int m = 0; m < 2; m++)
            #pragma unroll
            for (int n = 0; n < 2; n++) {
                acc0[m][n][0] = 0u; acc0[m][n][1] = 0u;
                acc1[m][n][0] = 0u; acc1[m][n][1] = 0u;
            }

        #pragma unroll
        for (int ks = 0; ks < 8; ks++) {
            unsigned a[2][4], bb0[4], bb1[4];
            ldsm4(a[0], aAddr0 + ks * 32);
            ldsm4(a[1], aAddr1 + ks * 32);
            ldsm4(bb0, kS0 + ks * 32);
            ldsm4(bb1, kS1 + ks * 32);
            #pragma unroll
            for (int m = 0; m < 2; m++) {
                mma16816h(acc0[m][0], a[m], &bb0[0]);
                mma16816h(acc0[m][1], a[m], &bb0[2]);
                mma16816h(acc1[m][0], a[m], &bb1[0]);
                mma16816h(acc1[m][1], a[m], &bb1[2]);
            }
        }

        nbar(barid);             // group done reading pair pp's slices

        if (pp + 2 < PAIRS) {
            fill_slice(2 * pp + 4);
            fill_slice(2 * pp + 5);
            cp_commit();
        }

        maxcollect(acc0, t0);
        maxcollect(acc1, t1);
    }
    __syncthreads();

    // dump candidates to global (row-major, no atomics)
    if (tid < BM) {
        const int r = tid;
        int c_ = cnt[r]; if (c_ > CAP) c_ = CAP;
        const int R = b * SEQ + q0 + r;
        g_cnt[R] = c_;
        for (int i = 0; i < c_; i++)
            g_candC[(size_t)R * CAP + i] = candC[r * CSTR + i];
    }
}

// ======================= Kernel B: tail =======================
__global__ __launch_bounds__(256, 4)
void tail_kernel(const float* __restrict__ Q, const float* __restrict__ K,
                 const float* __restrict__ V, float* __restrict__ O)
{
    __shared__ int   sCC[TROWS][CSTR];
    __shared__ float sCS[TROWS][CSTR];
    __shared__ int   sCnt[TROWS];
    __shared__ float sTau[TROWS], sZ[TROWS];

    const int tid  = threadIdx.x;
    const int lane = tid & 31;
    const int wid  = tid >> 5;
    const int R0   = blockIdx.x * TROWS;           // 32 rows, same batch (2048%32==0)
    const int b    = R0 / SEQ;

    const float* Kb = K + (size_t)b * SEQ * DIM;
    const float* Vb = V + (size_t)b * SEQ * DIM;

    // load counts + candidates
    if (tid < TROWS) sCnt[tid] = g_cnt[R0 + tid];
    __syncthreads();
    for (int i = tid; i < TROWS * CAP; i += 256) {
        int lr = i / CAP, j = i % CAP;
        if (j < sCnt[lr]) sCC[lr][j] = g_candC[(size_t)(R0 + lr) * CAP + j];
    }
    __syncthreads();

    // deterministic order: insertion sort by column (thread-per-row)
    if (tid < TROWS) {
        const int c_ = sCnt[tid];
        int* cc = sCC[tid];
        for (int i = 1; i < c_; i++) {
            int kv = cc[i]; int j = i - 1;
            while (j >= 0 && cc[j] > kv) { cc[j + 1] = cc[j]; j--; }
            cc[j + 1] = kv;
        }
    }
    __syncthreads();

    // exact fp32 rescore: warp-per-row (4 rows/warp), 4-way batched LDG
    for (int lr = wid; lr < TROWS; lr += 8) {
        const int c_ = sCnt[lr];
        const float4 qv = *(const float4*)(Q + (size_t)(R0 + lr) * DIM + lane * 4);
        for (int j0 = 0; j0 < c_; j0 += 4) {
            float4 kv[4];
            #pragma unroll
            for (int u = 0; u < 4; u++) {
                int j = j0 + u; if (j >= c_) j = c_ - 1;
                kv[u] = *(const float4*)(Kb + (size_t)sCC[lr][j] * DIM + lane * 4);
            }
            float d[4];
            #pragma unroll
            for (int u = 0; u < 4; u++) {
                float s = fmaf(qv.x, kv[u].x, 0.f);
                s = fmaf(qv.y, kv[u].y, s);
                s = fmaf(qv.z, kv[u].z, s);
                d[u] = fmaf(qv.w, kv[u].w, s);
            }
            #pragma unroll
            for (int s = 16; s > 0; s >>= 1) {
                d[0] += __shfl_xor_sync(0xffffffffu, d[0], s);
                d[1] += __shfl_xor_sync(0xffffffffu, d[1], s);
                d[2] += __shfl_xor_sync(0xffffffffu, d[2], s);
                d[3] += __shfl_xor_sync(0xffffffffu, d[3], s);
            }
            if (lane == 0) {
                #pragma unroll
                for (int u = 0; u < 4; u++)
                    if (j0 + u < c_) sCS[lr][j0 + u] = d[u];
            }
        }
    }
    __syncthreads();

    // bisection: thread-per-row, register-resident z
    if (tid < TROWS) {
        const int c_ = sCnt[tid];
        float* cs = sCS[tid];
        float tau, Zv;
        if (c_ <= ZREG) {
            float z[ZREG];
            float zmax = -3.0e38f;
            #pragma unroll
            for (int j = 0; j < ZREG; j++) {
                z[j] = (j < c_) ? 0.5f * cs[j] : -3.0e38f;
                zmax = fmaxf(zmax, z[j]);
            }
            float tmin = zmax - 1.0f;
            float tmax = zmax - 0.022097086912079608f;   // float32(2048^-0.5)
            tau = 0.5f * (tmin + tmax); Zv = 0.f;
            for (int it = 0; it < NITER; it++) {
                tau = 0.5f * (tmin + tmax);
                Zv = 0.f;
                #pragma unroll
                for (int j = 0; j < ZREG; j++) {
                    float dz = fmaxf(z[j] - tau, 0.f);
                    Zv = fmaf(dz, dz, Zv);
                }
                if (Zv >= 1.0f) tmin = tau; else tmax = tau;
            }
        } else {
            float smax = -3.0e38f;
            for (int j = 0; j < c_; j++) smax = fmaxf(smax, cs[j]);
            const float zmax = 0.5f * smax;
            float tmin = zmax - 1.0f;
            float tmax = zmax - 0.022097086912079608f;
            tau = 0.5f * (tmin + tmax); Zv = 0.f;
            for (int it = 0; it < NITER; it++) {
                tau = 0.5f * (tmin + tmax);
                Zv = 0.f;
                for (int j = 0; j < c_; j++) {
                    float dz = fmaxf(0.5f * cs[j] - tau, 0.f);
                    Zv = fmaf(dz, dz, Zv);
                }
                if (Zv >= 1.0f) tmin = tau; else tmax = tau;
            }
        }
        sTau[tid] = tau;
        sZ[tid]   = Zv;
    }
    __syncthreads();

    // sparse P@V: warp-per-row (4 rows/warp), 4-way batched V gather
    for (int lr = wid; lr < TROWS; lr += 8) {
        const int c_ = sCnt[lr];
        const float tau = sTau[lr];
        const float Zv  = sZ[lr];
        float ax = 0.f, ay = 0.f, az = 0.f, aw = 0.f;
        for (int j0 = 0; j0 < c_; j0 += 4) {
            float4 v[4]; float w[4];
            #pragma unroll
            for (int u = 0; u < 4; u++) {
                int j = j0 + u;
                bool ok = (j < c_);
                int jc = ok ? j : (c_ - 1);
                float dz = fmaxf(0.5f * sCS[lr][jc] - tau, 0.f);
                w[u] = ok ? (dz * dz) / Zv : 0.f;
                v[u] = *(const float4*)(Vb + (size_t)sCC[lr][jc] * DIM + lane * 4);
            }
            #pragma unroll
            for (int u = 0; u < 4; u++) {
                ax = fmaf(w[u], v[u].x, ax);
                ay = fmaf(w[u], v[u].y, ay);
                az = fmaf(w[u], v[u].z, az);
                aw = fmaf(w[u], v[u].w, aw);
            }
        }
        *(float4*)(O + (size_t)(R0 + lr) * DIM + lane * 4) = make_float4(ax, ay, az, aw);
    }
}

extern "C" void kernel_launch(void* const* d_in, const int* in_sizes, int n_in,
                              void* d_out, int out_size) {
    const float* Q = (const float*)d_in[0];
    const float* K = (const float*)d_in[1];
    const float* V = (const float*)d_in[2];
    float* O = (float*)d_out;

    cvt_kernel<<<2048, 256>>>(Q, K);

    cudaFuncSetAttribute(mainloop_kernel,
                         cudaFuncAttributeMaxDynamicSharedMemorySize, SMEM_BYTES);
    dim3 grid(QT, BATCH);
    mainloop_kernel<<<grid, NTHREADS, SMEM_BYTES>>>(Q, K);

    tail_kernel<<<(BATCH * SEQ) / TROWS, 256>>>(Q, K, V, O);
}

// round 16
// speedup vs baseline: 1.5797x; 1.2451x over previous
#include <cuda_runtime.h>
#include <cuda_fp16.h>

// SparseAttention (entmax-1.5), GB300 sm_103a. Round 15: harvest on R11.
//  - NITER 100->48 (bisection hits exact fp32 fixed point by ~iter 25; output
//    bit-identical, removes ~52 serialized iterations).
//  - cvt kernel: 8 elems/thread with 16B stores (was 8B) -> faster prologue.
//  - unchanged: 1024 thr / 32 warps, f16-accum mma.sync, pair A-reuse,
//    group-private K staging + named barriers, reg-resident bisection,
//    4-way batched rescore / P@V tails.

#define BATCH 8
#define SEQ   2048
#define DIM   128
#define BM    128
#define BN    128
#define NT    (SEQ / BN)       // 16
#define PAIRS (NT / 2)         // 8
#define QT    (SEQ / BM)       // 16
#define CAP   48
#define CSTR  49
#define QSTR  136              // f16 row stride (128+8 pad): 16B aligned, ldsm conflict-free
#define NITER 48
#define NTHREADS 1024
#define ZREG  12

#define TILE_B  (BM * QSTR * 2)                       // 34816
#define OFF_QHI  0
#define OFF_KHI  (OFF_QHI + TILE_B)                   // 34816
#define OFF_CS   (OFF_KHI + 4 * TILE_B)               // 174080
#define OFF_CC   (OFF_CS + BM * CSTR * 4)             // 199168
#define OFF_RM   (OFF_CC + BM * CSTR * 4)             // 224256
#define OFF_CNT  (OFF_RM + BM * 4)                    // 224768
#define OFF_TAU  (OFF_CNT + BM * 4)                   // 225280
#define OFF_Z    (OFF_TAU + BM * 4)                   // 225792
#define SMEM_BYTES (OFF_Z + BM * 4)                   // 226304

__device__ __half g_Qh[BATCH * SEQ * DIM];
__device__ __half g_Kh[BATCH * SEQ * DIM];

// 8 elems/thread, 16B stores. grid*block*8 = BATCH*SEQ*DIM -> grid 1024.
__global__ void cvt_kernel(const float* __restrict__ Q, const float* __restrict__ K) {
    size_t i = ((size_t)blockIdx.x * blockDim.x + threadIdx.x) * 8;
    float4 q0 = *(const float4*)(Q + i);
    float4 q1 = *(const float4*)(Q + i + 4);
    float4 k0 = *(const float4*)(K + i);
    float4 k1 = *(const float4*)(K + i + 4);
    __half2 qh[4], kh[4];
    qh[0] = __floats2half2_rn(q0.x, q0.y);
    qh[1] = __floats2half2_rn(q0.z, q0.w);
    qh[2] = __floats2half2_rn(q1.x, q1.y);
    qh[3] = __floats2half2_rn(q1.z, q1.w);
    kh[0] = __floats2half2_rn(k0.x, k0.y);
    kh[1] = __floats2half2_rn(k0.z, k0.w);
    kh[2] = __floats2half2_rn(k1.x, k1.y);
    kh[3] = __floats2half2_rn(k1.z, k1.w);
    *(uint4*)(g_Qh + i) = *(uint4*)qh;
    *(uint4*)(g_Kh + i) = *(uint4*)kh;
}

static __device__ __forceinline__ unsigned fenc(float f) {
    unsigned u = __float_as_uint(f);
    return (u & 0x80000000u) ? ~u : (u | 0x80000000u);
}
static __device__ __forceinline__ float fdec(unsigned e) {
    return (e & 0x80000000u) ? __uint_as_float(e & 0x7fffffffu)
                             : __uint_as_float(~e);
}
static __device__ __forceinline__ void cpasync16(unsigned dst, const void* src) {
    asm volatile("cp.async.cg.shared.global [%0], [%1], 16;\n" :: "r"(dst), "l"(src));
}
static __device__ __forceinline__ void cp_commit() {
    asm volatile("cp.async.commit_group;\n");
}
template <int N>
static __device__ __forceinline__ void cp_wait() {
    asm volatile("cp.async.wait_group %0;\n" :: "n"(N));
}
static __device__ __forceinline__ void nbar(int id) {
    asm volatile("bar.sync %0, %1;" :: "r"(id), "r"(128) : "memory");
}
static __device__ __forceinline__ void ldsm4(unsigned* r, unsigned addr) {
    asm volatile("ldmatrix.sync.aligned.m8n8.x4.shared.b16 {%0,%1,%2,%3}, [%4];\n"
                 : "=r"(r[0]), "=r"(r[1]), "=r"(r[2]), "=r"(r[3])
                 : "r"(addr) : "memory");
}
static __device__ __forceinline__ void mma16816h(unsigned* c, const unsigned* a, const unsigned* b) {
    asm volatile("mma.sync.aligned.m16n8k16.row.col.f16.f16.f16.f16 "
                 "{%0,%1}, {%2,%3,%4,%5}, {%6,%7}, {%0,%1};\n"
                 : "+r"(c[0]), "+r"(c[1])
                 : "r"(a[0]), "r"(a[1]), "r"(a[2]), "r"(a[3]),
                   "r"(b[0]), "r"(b[1]));
}

__global__ __launch_bounds__(NTHREADS, 1)
void entmax_attn_kernel(const float* __restrict__ Q, const float* __restrict__ K,
                        const float* __restrict__ V, float* __restrict__ O)
{
    extern __shared__ unsigned char smem[];
    float*    candS = (float*)(smem + OFF_CS);
    int*      candC = (int*)(smem + OFF_CC);
    unsigned* rowM  = (unsigned*)(smem + OFF_RM);
    int*      cnt   = (int*)(smem + OFF_CNT);
    float*    tauA  = (float*)(smem + OFF_TAU);
    float*    zA    = (float*)(smem + OFF_Z);

    const int tid  = threadIdx.x;
    const int lane = tid & 31;
    const int wid  = tid >> 5;
    const int b    = blockIdx.y;
    const int q0   = blockIdx.x * BM;

    const float* Qb = Q + ((size_t)b * SEQ + q0) * DIM;
    const float* Kb = K + (size_t)b * SEQ * DIM;
    const float* Vb = V + (size_t)b * SEQ * DIM;
    const __half* Qhb = g_Qh + ((size_t)b * SEQ + q0) * DIM;
    const __half* Khb = g_Kh + (size_t)b * SEQ * DIM;

    const unsigned smemB = (unsigned)__cvta_generic_to_shared(smem);
    const unsigned qS = smemB + OFF_QHI;

    // 4x8 warp grid: warp tile 32(M) x 16(N); group = wn (4 warps, contiguous tids)
    const int wm = wid & 3;
    const int wn = wid >> 2;
    const int g  = lane >> 2;
    const int t  = lane & 3;

    const int aRow = (lane & 7) + ((lane >> 3) & 1) * 8;
    const int aK   = ((lane >> 4) & 1) * 8;
    const int bGrp  = lane >> 3;
    const int bRow4 = ((bGrp >> 1) & 1) * 8 + (lane & 7);
    const int bK4   = (bGrp & 1) * 8;

    if (tid < BM) { rowM[tid] = 0u; cnt[tid] = 0; }

    // ---- Q fill: all 1024 threads, 2 chunks each ----
    {
        const int fr0 = tid >> 4;
        const int fc  = tid & 15;
        #pragma unroll
        for (int k = 0; k < 2; k++) {
            int r = fr0 + k * 64;
            cpasync16(qS + r * (QSTR * 2) + fc * 16, Qhb + r * DIM + fc * 8);
        }
    }

    // ---- group-private slice fill: 16 rows x 16 chunks / 128 threads = 2 each ----
    const int slr = (tid & 127) >> 3;
    const int sc0 = ((tid & 127) & 7) * 2;
    const int srow = wn * 16 + slr;
    auto fill_slice = [&](int nt) {
        unsigned dst = smemB + OFF_KHI + (nt & 3) * TILE_B + srow * (QSTR * 2);
        const __half* src = Khb + (size_t)nt * BN * DIM + srow * DIM;
        cpasync16(dst + sc0 * 16,       src + sc0 * 8);
        cpasync16(dst + (sc0 + 1) * 16, src + (sc0 + 1) * 8);
    };

    fill_slice(0);
    cp_commit();                 // G0 = Q + tile0
    fill_slice(1);
    cp_commit();                 // G1
    fill_slice(2);
    fill_slice(3);
    cp_commit();                 // G2 (pair1)
    cp_wait<2>();                // G0 done
    __syncthreads();             // Q visible to all warps

    const unsigned aAddr0 = qS + (unsigned)(((wm * 32 + aRow) * QSTR + aK) * 2);
    const unsigned aAddr1 = qS + (unsigned)(((wm * 32 + 16 + aRow) * QSTR + aK) * 2);
    const unsigned bOff   = (unsigned)(((wn * 16 + bRow4) * QSTR + bK4) * 2);
    const int barid = wn + 1;

    auto maxcollect = [&](unsigned (&acc)[2][2][2], int nt) {
        float qm[2][2];
        #pragma unroll
        for (int m = 0; m < 2; m++) {
            #pragma unroll
            for (int h = 0; h < 2; h++) {
                __half2 x = __hmax2(*(__half2*)&acc[m][0][h], *(__half2*)&acc[m][1][h]);
                float2 f = __half22float2(x);
                float lm = fmaxf(f.x, f.y);
                lm = fmaxf(lm, __shfl_xor_sync(0xffffffffu, lm, 1));
                lm = fmaxf(lm, __shfl_xor_sync(0xffffffffu, lm, 2));
                qm[m][h] = lm;
                if ((lane & 3) == 0) {
                    const int r = wm * 32 + m * 16 + h * 8 + g;
                    if (fenc(lm) > rowM[r]) atomicMax(&rowM[r], fenc(lm));
                }
            }
        }
        __syncwarp();
        #pragma unroll
        for (int m = 0; m < 2; m++) {
            #pragma unroll
            for (int h = 0; h < 2; h++) {
                const int r = wm * 32 + m * 16 + h * 8 + g;
                const float thr = fdec(rowM[r]) - 3.5f;
                if (qm[m][h] > thr) {
                    #pragma unroll
                    for (int n = 0; n < 2; n++) {
                        float2 f = __half22float2(*(__half2*)&acc[m][n][h]);
                        #pragma unroll
                        for (int e = 0; e < 2; e++) {
                            float s = (e == 0) ? f.x : f.y;
                            if (s > thr) {
                                int p = atomicAdd(&cnt[r], 1);
                                if (p < CAP)
                                    candC[r * CSTR + p] = nt * BN + wn * 16 + n * 8 + t * 2 + e;
                            }
                        }
                    }
                }
            }
        }
    };

    for (int pp = 0; pp < PAIRS; pp++) {
        {
            const int commits = 3 + (pp < PAIRS - 2 ? pp : PAIRS - 2);
            const int out     = commits - (pp + 2);
            if (out <= 0)      cp_wait<0>();
            else if (out == 1) cp_wait<1>();
            else               cp_wait<2>();
        }
        nbar(barid);             // group's slices for pair pp visible

        const int t0 = 2 * pp, t1 = 2 * pp + 1;
        const unsigned kS0 = smemB + OFF_KHI + (t0 & 3) * TILE_B + bOff;
        const unsigned kS1 = smemB + OFF_KHI + (t1 & 3) * TILE_B + bOff;

        unsigned acc0[2][2][2], acc1[2][2][2];
        #pragma unroll
        for (int m = 0; m < 2; m++)
            #pragma unroll
            for (int n = 0; n < 2; n++) {
                acc0[m][n][0] = 0u; acc0[m][n][1] = 0u;
                acc1[m][n][0] = 0u; acc1[m][n][1] = 0u;
            }

        #pragma unroll
        for (int ks = 0; ks < 8; ks++) {
            unsigned a[2][4], bb0[4], bb1[4];
            ldsm4(a[0], aAddr0 + ks * 32);
            ldsm4(a[1], aAddr1 + ks * 32);
            ldsm4(bb0, kS0 + ks * 32);
            ldsm4(bb1, kS1 + ks * 32);
            #pragma unroll
            for (int m = 0; m < 2; m++) {
                mma16816h(acc0[m][0], a[m], &bb0[0]);
                mma16816h(acc0[m][1], a[m], &bb0[2]);
                mma16816h(acc1[m][0], a[m], &bb1[0]);
                mma16816h(acc1[m][1], a[m], &bb1[2]);
            }
        }

        nbar(barid);             // group done reading pair pp's slices

        if (pp + 2 < PAIRS) {
            fill_slice(2 * pp + 4);
            fill_slice(2 * pp + 5);
            cp_commit();
        }

        maxcollect(acc0, t0);    // overlaps group fills
        maxcollect(acc1, t1);
    }
    __syncthreads();

    // ---- deterministic order: per-row insertion sort by column (indices) ----
    if (tid < BM) {
        const int r = tid;
        int c_ = cnt[r]; if (c_ > CAP) { c_ = CAP; cnt[r] = CAP; }
        int* cc = candC + r * CSTR;
        for (int i = 1; i < c_; i++) {
            int kv = cc[i]; int j = i - 1;
            while (j >= 0 && cc[j] > kv) { cc[j + 1] = cc[j]; j--; }
            cc[j + 1] = kv;
        }
    }
    __syncthreads();

    // ---- exact fp32 rescore: warp-per-row (4 rows/warp), 4-way batched LDG ----
    for (int r = wid; r < BM; r += 32) {
        const int c_ = cnt[r];
        float* cs = candS + r * CSTR;
        int*   cc = candC + r * CSTR;
        const float4 qv = *(const float4*)(Qb + (size_t)r * DIM + lane * 4);
        for (int j0 = 0; j0 < c_; j0 += 4) {
            float4 kv[4];
            #pragma unroll
            for (int u = 0; u < 4; u++) {
                int j = j0 + u; if (j >= c_) j = c_ - 1;
                kv[u] = *(const float4*)(Kb + (size_t)cc[j] * DIM + lane * 4);
            }
            float d[4];
            #pragma unroll
            for (int u = 0; u < 4; u++) {
                float s = fmaf(qv.x, kv[u].x, 0.f);
                s = fmaf(qv.y, kv[u].y, s);
                s = fmaf(qv.z, kv[u].z, s);
                d[u] = fmaf(qv.w, kv[u].w, s);
            }
            #pragma unroll
            for (int s = 16; s > 0; s >>= 1) {
                d[0] += __shfl_xor_sync(0xffffffffu, d[0], s);
                d[1] += __shfl_xor_sync(0xffffffffu, d[1], s);
                d[2] += __shfl_xor_sync(0xffffffffu, d[2], s);
                d[3] += __shfl_xor_sync(0xffffffffu, d[3], s);
            }
            if (lane == 0) {
                #pragma unroll
                for (int u = 0; u < 4; u++)
                    if (j0 + u < c_) cs[j0 + u] = d[u];
            }
        }
    }
    __syncthreads();

    // ---- bisection: thread-per-row, register-resident z for c_<=ZREG ----
    if (tid < BM) {
        const int r = tid;
        const int c_ = cnt[r];
        float* cs = candS + r * CSTR;
        float tau, Zv;

        if (c_ <= ZREG) {
            float z[ZREG];
            float zmax = -3.0e38f;
            #pragma unroll
            for (int j = 0; j < ZREG; j++) {
                z[j] = (j < c_) ? 0.5f * cs[j] : -3.0e38f;
                zmax = fmaxf(zmax, z[j]);
            }
            float tmin = zmax - 1.0f;
            float tmax = zmax - 0.022097086912079608f;   // float32(2048^-0.5)
            tau = 0.5f * (tmin + tmax); Zv = 0.f;
            for (int it = 0; it < NITER; it++) {
                tau = 0.5f * (tmin + tmax);
                Zv = 0.f;
                #pragma unroll
                for (int j = 0; j < ZREG; j++) {
                    float dz = fmaxf(z[j] - tau, 0.f);
                    Zv = fmaf(dz, dz, Zv);
                }
                if (Zv >= 1.0f) tmin = tau; else tmax = tau;
            }
        } else {
            float smax = -3.0e38f;
            for (int j = 0; j < c_; j++) smax = fmaxf(smax, cs[j]);
            const float zmax = 0.5f * smax;
            float tmin = zmax - 1.0f;
            float tmax = zmax - 0.022097086912079608f;
            tau = 0.5f * (tmin + tmax); Zv = 0.f;
            for (int it = 0; it < NITER; it++) {
                tau = 0.5f * (tmin + tmax);
                Zv = 0.f;
                for (int j = 0; j < c_; j++) {
                    float dz = fmaxf(0.5f * cs[j] - tau, 0.f);
                    Zv = fmaf(dz, dz, Zv);
                }
                if (Zv >= 1.0f) tmin = tau; else tmax = tau;
            }
        }
        tauA[r] = tau;
        zA[r]   = Zv;
    }
    __syncthreads();

    // ---- sparse P@V: 32 warps x 4 rows, 4-way batched V gather ----
    for (int rr = 0; rr < 4; rr++) {
        const int r = wid * 4 + rr;
        const int c_ = cnt[r];
        const float tau = tauA[r];
        const float Zv  = zA[r];
        float ax = 0.f, ay = 0.f, az = 0.f, aw = 0.f;
        for (int j0 = 0; j0 < c_; j0 += 4) {
            float4 v[4]; float w[4];
            #pragma unroll
            for (int u = 0; u < 4; u++) {
                int j = j0 + u;
                bool ok = (j < c_);
                int jc = ok ? j : (c_ - 1);
                float dz = fmaxf(0.5f * candS[r * CSTR + jc] - tau, 0.f);
                w[u] = ok ? (dz * dz) / Zv : 0.f;
                v[u] = *(const float4*)(Vb + (size_t)candC[r * CSTR + jc] * DIM + lane * 4);
            }
            #pragma unroll
            for (int u = 0; u < 4; u++) {
                ax = fmaf(w[u], v[u].x, ax);
                ay = fmaf(w[u], v[u].y, ay);
                az = fmaf(w[u], v[u].z, az);
                aw = fmaf(w[u], v[u].w, aw);
            }
        }
        *(float4*)(O + ((size_t)b * SEQ + q0 + r) * DIM + lane * 4) = make_float4(ax, ay, az, aw);
    }
}

extern "C" void kernel_launch(void* const* d_in, const int* in_sizes, int n_in,
                              void* d_out, int out_size) {
    const float* Q = (const float*)d_in[0];
    const float* K = (const float*)d_in[1];
    const float* V = (const float*)d_in[2];
    float* O = (float*)d_out;

    cvt_kernel<<<1024, 256>>>(Q, K);   // 1024*256*8 = BATCH*SEQ*DIM exactly

    cudaFuncSetAttribute(entmax_attn_kernel,
                         cudaFuncAttributeMaxDynamicSharedMemorySize, SMEM_BYTES);
    dim3 grid(QT, BATCH);
    entmax_attn_kernel<<<grid, NTHREADS, SMEM_BYTES>>>(Q, K, V, O);
}